// round 1
// baseline (speedup 1.0000x reference)
#include <cuda_runtime.h>
#include <cstdint>
#include <math.h>

#define CC 1024
#define HH 64
#define NROWS (256*1024)

// Scratch (allocation-free rule: __device__ globals)
__device__ float g_adj[2*CC];                       // clipped adjacency weights
__device__ float g_mnext[(size_t)NROWS * HH];       // 64 MB intermediate m_next

// ---------------------------------------------------------------------------
// Kernel 1: adj[k][d] = clip( sum_c mask0[c]*graphs[k][c][d] / denom, -5, 5 )
// mask0 is binary with ~5 nonzeros -> compact then gather.
// ---------------------------------------------------------------------------
__global__ void adj_kernel(const int* __restrict__ qt,
                           const float* __restrict__ oh,
                           const float* __restrict__ graphs)
{
    __shared__ int   s_idx[CC];
    __shared__ float s_val[CC];
    __shared__ int   s_cnt;
    __shared__ float s_sum;

    int t = threadIdx.x;
    if (t == 0) { s_cnt = 0; s_sum = 0.f; }
    __syncthreads();

    int q0 = qt[0];
    float m = oh[(size_t)q0 * CC + t];
    if (m != 0.f) {
        int p = atomicAdd(&s_cnt, 1);
        s_idx[p] = t; s_val[p] = m;
        atomicAdd(&s_sum, m);
    }
    __syncthreads();

    float denom = fmaxf(s_sum, 1.f);
    int nnz = s_cnt;
    for (int k = 0; k < 2; k++) {
        float acc = 0.f;
        for (int i = 0; i < nnz; i++)
            acc += s_val[i] * graphs[(size_t)k*CC*CC + (size_t)s_idx[i]*CC + t];
        g_adj[k*CC + t] = fminf(fmaxf(acc / denom, -5.f), 5.f);
    }
}

// ---------------------------------------------------------------------------
// Kernel 2 (persistent): compute m_next for all B*C rows, 128-row tiles.
// For mask==0 rows: nb_k = clip(relu(relu(u@Wn1_lo[k]+bn1)@Wn2[k]+bn2),-5,5)
//                   with u = clip([ht,kc],-5,5) (only lower half of Wn1 needed)
// For mask==1 rows: self MLP on RAW x (rare, cooperative path).
// ---------------------------------------------------------------------------
__global__ void __launch_bounds__(256) f1_kernel(
    const int*   __restrict__ qt,  const float* __restrict__ ht,
    const float* __restrict__ oh,  const float* __restrict__ kc,
    const float* __restrict__ nwp,
    const float* __restrict__ Ws1, const float* __restrict__ bs1,
    const float* __restrict__ Ws2, const float* __restrict__ bs2,
    const float* __restrict__ Wn1, const float* __restrict__ bn1,
    const float* __restrict__ Wn2, const float* __restrict__ bn2)
{
    extern __shared__ float smem[];
    float* sWn1  = smem;                 // 2*128*64 = 16384
    float* sWn2  = sWn1 + 16384;         // 2*64*64  = 8192
    float* sbn1  = sWn2 + 8192;          // 128
    float* sbn2  = sbn1 + 128;           // 128
    float* U     = sbn2 + 128;           // 128*132  = 16896 (pad 132)
    float* H1    = U + 16896;            // 128*68   = 8704  (pad 68)
    float* rmask = H1 + 8704;            // 128
    float* radj0 = rmask + 128;          // 128
    float* radj1 = radj0 + 128;          // 128
    __shared__ int s_mcnt;
    __shared__ int s_mrows[128];

    int tid = threadIdx.x;

    // Load weights once per block (persistent)
    for (int i = tid; i < 2*128*64; i += 256) {
        int k = i >> 13; int rc = i & 8191;
        sWn1[i] = Wn1[k*16384 + 8192 + rc];   // lower half: rows 128..255 of Wn1[k]
    }
    for (int i = tid; i < 2*64*64; i += 256) sWn2[i] = Wn2[i];
    if (tid < 128) { sbn1[tid] = bn1[tid]; sbn2[tid] = bn2[tid]; }
    float w = fminf(fmaxf(nwp[0], 0.1f), 0.9f);
    __syncthreads();

    int tr = tid >> 4, tc = tid & 15;
    int rbase = tr * 8, cbase = tc * 4;

    for (int tile = blockIdx.x; tile < NROWS/128; tile += gridDim.x) {
        int row0 = tile << 7;
        if (tid == 0) s_mcnt = 0;
        __syncthreads();

        // Load U = clip([ht, kc], -5, 5), mask, adj per row
        for (int i = tid; i < 128*128; i += 256) {
            int r = i >> 7, j = i & 127;
            int gid = row0 + r; int c = gid & 1023;
            float v = (j < 64) ? ht[(size_t)gid*64 + j] : kc[c*64 + (j-64)];
            U[r*132 + j] = fminf(fmaxf(v, -5.f), 5.f);
        }
        if (tid < 128) {
            int gid = row0 + tid; int b = gid >> 10; int c = gid & 1023;
            float m = oh[(size_t)qt[b]*CC + c];
            rmask[tid] = m;
            radj0[tid] = g_adj[c];
            radj1[tid] = g_adj[CC + c];
            if (m > 0.5f) { int p = atomicAdd(&s_mcnt, 1); s_mrows[p] = tid; }
        }
        __syncthreads();

        float nf[8][4];
        for (int k = 0; k < 2; k++) {
            // Stage A: H1 = relu(U @ Wn1_lo[k] + bn1[k])   (128x128 @ 128x64)
            float acc[8][4];
            {
                float4 b4 = *(const float4*)(sbn1 + k*64 + cbase);
                #pragma unroll
                for (int i = 0; i < 8; i++) {
                    acc[i][0]=b4.x; acc[i][1]=b4.y; acc[i][2]=b4.z; acc[i][3]=b4.w;
                }
            }
            const float* Wk = sWn1 + k*8192 + cbase;
            #pragma unroll 4
            for (int kk = 0; kk < 128; kk++) {
                float4 wv = *(const float4*)(Wk + kk*64);
                #pragma unroll
                for (int i = 0; i < 8; i++) {
                    float u = U[(rbase+i)*132 + kk];
                    acc[i][0] = fmaf(u, wv.x, acc[i][0]);
                    acc[i][1] = fmaf(u, wv.y, acc[i][1]);
                    acc[i][2] = fmaf(u, wv.z, acc[i][2]);
                    acc[i][3] = fmaf(u, wv.w, acc[i][3]);
                }
            }
            #pragma unroll
            for (int i = 0; i < 8; i++) {
                float4 hv;
                hv.x = fmaxf(acc[i][0], 0.f); hv.y = fmaxf(acc[i][1], 0.f);
                hv.z = fmaxf(acc[i][2], 0.f); hv.w = fmaxf(acc[i][3], 0.f);
                *(float4*)(H1 + (rbase+i)*68 + cbase) = hv;
            }
            __syncthreads();

            // Stage B: nb = clip(relu(H1 @ Wn2[k] + bn2[k]), -5, 5)
            {
                float4 b4 = *(const float4*)(sbn2 + k*64 + cbase);
                #pragma unroll
                for (int i = 0; i < 8; i++) {
                    acc[i][0]=b4.x; acc[i][1]=b4.y; acc[i][2]=b4.z; acc[i][3]=b4.w;
                }
            }
            const float* W2k = sWn2 + k*4096 + cbase;
            #pragma unroll 4
            for (int kk = 0; kk < 64; kk++) {
                float4 wv = *(const float4*)(W2k + kk*64);
                #pragma unroll
                for (int i = 0; i < 8; i++) {
                    float u = H1[(rbase+i)*68 + kk];
                    acc[i][0] = fmaf(u, wv.x, acc[i][0]);
                    acc[i][1] = fmaf(u, wv.y, acc[i][1]);
                    acc[i][2] = fmaf(u, wv.z, acc[i][2]);
                    acc[i][3] = fmaf(u, wv.w, acc[i][3]);
                }
            }
            #pragma unroll
            for (int i = 0; i < 8; i++) {
                float a = (k == 0) ? radj0[rbase+i] : radj1[rbase+i];
                #pragma unroll
                for (int j = 0; j < 4; j++) {
                    float nb = fminf(fmaxf(acc[i][j], 0.f), 5.f);
                    float v = a * nb;
                    if (k == 0)
                        nf[i][j] = fminf(fmaxf(v, -5.f), 5.f);   // clip(adj0*nb0)
                    else
                        nf[i][j] = fminf(fmaxf(w*nf[i][j] + (1.f - w)*v, -5.f), 5.f);
                }
            }
            __syncthreads();   // H1 free for next k / scratch
        }

        // Write m_next for unmasked rows
        #pragma unroll
        for (int i = 0; i < 8; i++) {
            int r = rbase + i;
            if (rmask[r] <= 0.5f) {
                float4 o;
                o.x = fminf(fmaxf(nf[i][0], -50.f), 50.f);
                o.y = fminf(fmaxf(nf[i][1], -50.f), 50.f);
                o.z = fminf(fmaxf(nf[i][2], -50.f), 50.f);
                o.w = fminf(fmaxf(nf[i][3], -50.f), 50.f);
                *(float4*)(&g_mnext[(size_t)(row0 + r)*64 + cbase]) = o;
            }
        }

        // Rare masked rows: self MLP on RAW x (cooperative, weights via L2)
        int mcnt = s_mcnt;
        for (int mi = 0; mi < mcnt; mi++) {
            int r = s_mrows[mi]; int gid = row0 + r; int c = gid & 1023;
            float* xr = H1; float* hb = H1 + 128;   // scratch (H1 free)
            if (tid < 128)
                xr[tid] = (tid < 64) ? ht[(size_t)gid*64 + tid] : kc[c*64 + tid - 64];
            __syncthreads();
            if (tid < 64) {
                float a = bs1[tid];
                for (int j = 0; j < 128; j++) a = fmaf(xr[j], Ws1[j*64 + tid], a);
                hb[tid] = fmaxf(a, 0.f);
            }
            __syncthreads();
            if (tid < 64) {
                float a = bs2[tid];
                for (int j = 0; j < 64; j++) a = fmaf(hb[j], Ws2[j*64 + tid], a);
                a = fminf(fmaxf(a, 0.f), 10.f);              // clip(relu, -10, 10)
                g_mnext[(size_t)gid*64 + tid] = fminf(fmaxf(a, -50.f), 50.f);
            }
            __syncthreads();
        }
        __syncthreads();   // before next tile overwrites U
    }
}

// ---------------------------------------------------------------------------
// Kernel 3 (persistent): edge-gate + GRU + output head, 64-row tiles.
// ---------------------------------------------------------------------------
__device__ __forceinline__ float sigf(float x) { return 1.f / (1.f + expf(-x)); }

__global__ void __launch_bounds__(256) f2_kernel(
    const float* __restrict__ ht,  const float* __restrict__ ea_w,
    const float* __restrict__ We,  const float* __restrict__ be,
    const float* __restrict__ Wa,  const float* __restrict__ ba,
    const float* __restrict__ Wih, const float* __restrict__ bih,
    const float* __restrict__ Whh, const float* __restrict__ bhh,
    const float* __restrict__ Wp,  const float* __restrict__ bp,
    float* __restrict__ out)
{
    extern __shared__ float smem[];
    float* sWe  = smem;                 // 4096
    float* sWa  = sWe  + 4096;          // 4096
    float* sWih = sWa  + 4096;          // 12288
    float* sWhh = sWih + 12288;         // 12288
    float* sbe  = sWhh + 12288;         // 64
    float* sba  = sbe  + 64;            // 64
    float* sbih = sba  + 64;            // 192
    float* sbhh = sbih + 192;           // 192
    float* sWp  = sbhh + 192;           // 64
    float* M    = sWp  + 64;            // 64*66 = 4224 (m_next, then res in-place)
    float* Ht   = M    + 4224;          // 4224
    float* Rt   = Ht   + 4224;          // 4224
    float* Zt   = Rt   + 4224;          // 4224
    float* grow = Zt   + 4224;          // 64

    int tid = threadIdx.x;
    for (int i = tid; i < 4096;  i += 256) { sWe[i] = We[i]; sWa[i] = Wa[i]; }
    for (int i = tid; i < 12288; i += 256) { sWih[i] = Wih[i]; sWhh[i] = Whh[i]; }
    if (tid < 64)  { sbe[tid] = be[tid]; sba[tid] = ba[tid]; sWp[tid] = Wp[tid]; }
    if (tid < 192) { sbih[tid] = bih[tid]; sbhh[tid] = bhh[tid]; }
    float bpv = bp[0];
    __syncthreads();

    int tr = tid >> 4, tc = tid & 15;
    int rbase = tr * 4, cbase = tc * 4;

    for (int tile = blockIdx.x; tile < NROWS/64; tile += gridDim.x) {
        int row0 = tile << 6;
        for (int i = tid; i < 64*64; i += 256) {
            int r = i >> 6, j = i & 63;
            M [r*66 + j] = g_mnext[(size_t)(row0 + r)*64 + j];
            Ht[r*66 + j] = ht     [(size_t)(row0 + r)*64 + j];
        }
        if (tid < 64) grow[tid] = ea_w[(row0 + tid) & 1023];
        __syncthreads();

        // Phase A: S = M@We+be, T = M@Wa+ba; res = m - g*sig(S)*m + g*tanh(T)
        float accS[4][4], accT[4][4];
        {
            float4 b1 = *(const float4*)(sbe + cbase);
            float4 b2 = *(const float4*)(sba + cbase);
            #pragma unroll
            for (int i = 0; i < 4; i++) {
                accS[i][0]=b1.x; accS[i][1]=b1.y; accS[i][2]=b1.z; accS[i][3]=b1.w;
                accT[i][0]=b2.x; accT[i][1]=b2.y; accT[i][2]=b2.z; accT[i][3]=b2.w;
            }
        }
        #pragma unroll 4
        for (int kk = 0; kk < 64; kk++) {
            float4 we4 = *(const float4*)(sWe + kk*64 + cbase);
            float4 wa4 = *(const float4*)(sWa + kk*64 + cbase);
            #pragma unroll
            for (int i = 0; i < 4; i++) {
                float u = M[(rbase+i)*66 + kk];
                accS[i][0]=fmaf(u,we4.x,accS[i][0]); accS[i][1]=fmaf(u,we4.y,accS[i][1]);
                accS[i][2]=fmaf(u,we4.z,accS[i][2]); accS[i][3]=fmaf(u,we4.w,accS[i][3]);
                accT[i][0]=fmaf(u,wa4.x,accT[i][0]); accT[i][1]=fmaf(u,wa4.y,accT[i][1]);
                accT[i][2]=fmaf(u,wa4.z,accT[i][2]); accT[i][3]=fmaf(u,wa4.w,accT[i][3]);
            }
        }
        __syncthreads();   // all GEMM reads of M done
        #pragma unroll
        for (int i = 0; i < 4; i++) {
            int r = rbase + i; float g = grow[r];
            #pragma unroll
            for (int j = 0; j < 4; j++) {
                float m = M[r*66 + cbase + j];
                float s = sigf(accS[i][j]);
                float t = tanhf(accT[i][j]);
                M[r*66 + cbase + j] = m - g*s*m + g*t;    // res (in place)
            }
        }
        __syncthreads();

        // Phase B: r and z gates
        #pragma unroll
        for (int gate = 0; gate < 2; gate++) {
            float acc[4][4];
            {
                const float* bi = sbih + gate*64 + cbase;
                const float* bh = sbhh + gate*64 + cbase;
                #pragma unroll
                for (int i = 0; i < 4; i++)
                    #pragma unroll
                    for (int j = 0; j < 4; j++) acc[i][j] = bi[j] + bh[j];
            }
            #pragma unroll 2
            for (int kk = 0; kk < 64; kk++) {
                float4 wi = *(const float4*)(sWih + kk*192 + gate*64 + cbase);
                float4 wh = *(const float4*)(sWhh + kk*192 + gate*64 + cbase);
                #pragma unroll
                for (int i = 0; i < 4; i++) {
                    float u = M [(rbase+i)*66 + kk];
                    float h = Ht[(rbase+i)*66 + kk];
                    acc[i][0] = fmaf(u, wi.x, fmaf(h, wh.x, acc[i][0]));
                    acc[i][1] = fmaf(u, wi.y, fmaf(h, wh.y, acc[i][1]));
                    acc[i][2] = fmaf(u, wi.z, fmaf(h, wh.z, acc[i][2]));
                    acc[i][3] = fmaf(u, wi.w, fmaf(h, wh.w, acc[i][3]));
                }
            }
            float* dst = gate ? Zt : Rt;
            #pragma unroll
            for (int i = 0; i < 4; i++)
                #pragma unroll
                for (int j = 0; j < 4; j++)
                    dst[(rbase+i)*66 + cbase + j] = sigf(acc[i][j]);
        }
        __syncthreads();

        // Phase C: n gate (needs in_ and hn separate), h_next, y = sig(h@Wp+bp)
        float accI[4][4], accH[4][4];
        {
            const float* bi = sbih + 128 + cbase;
            const float* bh = sbhh + 128 + cbase;
            #pragma unroll
            for (int i = 0; i < 4; i++)
                #pragma unroll
                for (int j = 0; j < 4; j++) { accI[i][j] = bi[j]; accH[i][j] = bh[j]; }
        }
        #pragma unroll 2
        for (int kk = 0; kk < 64; kk++) {
            float4 wi = *(const float4*)(sWih + kk*192 + 128 + cbase);
            float4 wh = *(const float4*)(sWhh + kk*192 + 128 + cbase);
            #pragma unroll
            for (int i = 0; i < 4; i++) {
                float u = M [(rbase+i)*66 + kk];
                float h = Ht[(rbase+i)*66 + kk];
                accI[i][0]=fmaf(u,wi.x,accI[i][0]); accI[i][1]=fmaf(u,wi.y,accI[i][1]);
                accI[i][2]=fmaf(u,wi.z,accI[i][2]); accI[i][3]=fmaf(u,wi.w,accI[i][3]);
                accH[i][0]=fmaf(h,wh.x,accH[i][0]); accH[i][1]=fmaf(h,wh.y,accH[i][1]);
                accH[i][2]=fmaf(h,wh.z,accH[i][2]); accH[i][3]=fmaf(h,wh.w,accH[i][3]);
            }
        }
        float wpj[4];
        { float4 wp4 = *(const float4*)(sWp + cbase);
          wpj[0]=wp4.x; wpj[1]=wp4.y; wpj[2]=wp4.z; wpj[3]=wp4.w; }
        #pragma unroll
        for (int i = 0; i < 4; i++) {
            int r = rbase + i;
            float py = 0.f;
            #pragma unroll
            for (int j = 0; j < 4; j++) {
                float rr = Rt[r*66 + cbase + j];
                float z  = Zt[r*66 + cbase + j];
                float hv = Ht[r*66 + cbase + j];
                float n  = tanhf(accI[i][j] + rr*accH[i][j]);
                float hn = (1.f - z)*n + z*hv;
                py = fmaf(hn, wpj[j], py);
            }
            py += __shfl_down_sync(0xffffffffu, py, 8, 16);
            py += __shfl_down_sync(0xffffffffu, py, 4, 16);
            py += __shfl_down_sync(0xffffffffu, py, 2, 16);
            py += __shfl_down_sync(0xffffffffu, py, 1, 16);
            if (tc == 0) out[row0 + r] = sigf(py + bpv);
        }
        __syncthreads();
    }
}

// ---------------------------------------------------------------------------
extern "C" void kernel_launch(void* const* d_in, const int* in_sizes, int n_in,
                              void* d_out, int out_size)
{
    const int*   qt  = (const int*)  d_in[1];
    const float* ht  = (const float*)d_in[2];
    const float* oh  = (const float*)d_in[3];
    const float* kc  = (const float*)d_in[4];
    const float* gr  = (const float*)d_in[5];
    const float* nw  = (const float*)d_in[6];
    const float* Ws1 = (const float*)d_in[7];
    const float* bs1 = (const float*)d_in[8];
    const float* Ws2 = (const float*)d_in[9];
    const float* bs2 = (const float*)d_in[10];
    const float* Wn1 = (const float*)d_in[11];
    const float* bn1 = (const float*)d_in[12];
    const float* Wn2 = (const float*)d_in[13];
    const float* bn2 = (const float*)d_in[14];
    const float* ea  = (const float*)d_in[15];
    const float* We  = (const float*)d_in[16];
    const float* be  = (const float*)d_in[17];
    const float* Wa  = (const float*)d_in[18];
    const float* ba  = (const float*)d_in[19];
    const float* Wih = (const float*)d_in[20];
    const float* bih = (const float*)d_in[21];
    const float* Whh = (const float*)d_in[22];
    const float* bhh = (const float*)d_in[23];
    const float* Wp  = (const float*)d_in[24];
    const float* bp  = (const float*)d_in[25];
    float* out = (float*)d_out;

    int smc = 148;
    if (cudaDeviceGetAttribute(&smc, cudaDevAttrMultiProcessorCount, 0) != cudaSuccess || smc <= 0)
        smc = 148;

    size_t smem1 = (size_t)(16384 + 8192 + 128 + 128 + 16896 + 8704 + 128 + 128 + 128) * 4; // 203264 B
    size_t smem2 = (size_t)(4096 + 4096 + 12288 + 12288 + 64 + 64 + 192 + 192 + 64 + 4*4224 + 64) * 4; // 201216 B
    cudaFuncSetAttribute(f1_kernel, cudaFuncAttributeMaxDynamicSharedMemorySize, (int)smem1);
    cudaFuncSetAttribute(f2_kernel, cudaFuncAttributeMaxDynamicSharedMemorySize, (int)smem2);

    adj_kernel<<<1, 1024>>>(qt, oh, gr);
    f1_kernel<<<smc, 256, smem1>>>(qt, ht, oh, kc, nw, Ws1, bs1, Ws2, bs2, Wn1, bn1, Wn2, bn2);
    f2_kernel<<<smc, 256, smem2>>>(ht, ea, We, be, Wa, ba, Wih, bih, Whh, bhh, Wp, bp, out);
}

// round 2
// speedup vs baseline: 1.4369x; 1.4369x over previous
#include <cuda_runtime.h>
#include <cstdint>
#include <math.h>

#define CC 1024
#define NROWS (256*1024)
#define RP1 132     // f1 transposed row pad (mult of 4 for b64x2 alignment)
#define RP2 68      // f2 transposed row pad

typedef unsigned long long ull;

// Scratch (allocation-free rule: __device__ globals)
__device__ float g_adj[2*CC];
__device__ float g_kcbase[2*CC*64];                 // per-(k,c) folded kc@Wn1_kc + bn1
__device__ float g_mnext[(size_t)NROWS * 64];       // 64 MB intermediate m_next

// ---- packed f32x2 helpers -------------------------------------------------
__device__ __forceinline__ ull dup2(float x){ ull r; asm("mov.b64 %0,{%1,%1};":"=l"(r):"f"(x)); return r; }
__device__ __forceinline__ ull pk2(float lo, float hi){ ull r; asm("mov.b64 %0,{%1,%2};":"=l"(r):"f"(lo),"f"(hi)); return r; }
__device__ __forceinline__ float2 up2(ull v){ float2 f; asm("mov.b64 {%0,%1},%2;":"=f"(f.x),"=f"(f.y):"l"(v)); return f; }
__device__ __forceinline__ void fma2(ull&d, ull a, ull b){ asm("fma.rn.f32x2 %0,%1,%2,%0;":"+l"(d):"l"(a),"l"(b)); }

__device__ __forceinline__ float clampf(float v,float lo,float hi){ return fminf(fmaxf(v,lo),hi); }
__device__ __forceinline__ float sigf(float x){ return __fdividef(1.f, 1.f + __expf(-x)); }
__device__ __forceinline__ float tanhfast(float x){
    float t = __expf(-2.f*fabsf(x));
    float r = __fdividef(1.f - t, 1.f + t);
    return copysignf(r, x);
}

// ---------------------------------------------------------------------------
// adj: mask0 has ~5 nonzeros -> compact + gather
// ---------------------------------------------------------------------------
__global__ void adj_kernel(const int* __restrict__ qt,
                           const float* __restrict__ oh,
                           const float* __restrict__ graphs)
{
    __shared__ int   s_idx[CC];
    __shared__ float s_val[CC];
    __shared__ int   s_cnt;
    __shared__ float s_sum;

    int t = threadIdx.x;
    if (t == 0) { s_cnt = 0; s_sum = 0.f; }
    __syncthreads();

    int q0 = qt[0];
    float m = oh[(size_t)q0 * CC + t];
    if (m != 0.f) {
        int p = atomicAdd(&s_cnt, 1);
        s_idx[p] = t; s_val[p] = m;
        atomicAdd(&s_sum, m);
    }
    __syncthreads();

    float denom = fmaxf(s_sum, 1.f);
    int nnz = s_cnt;
    for (int k = 0; k < 2; k++) {
        float acc = 0.f;
        for (int i = 0; i < nnz; i++)
            acc += s_val[i] * graphs[(size_t)k*CC*CC + (size_t)s_idx[i]*CC + t];
        g_adj[k*CC + t] = clampf(acc / denom, -5.f, 5.f);
    }
}

// ---------------------------------------------------------------------------
// kcbase[k][c][j] = bn1[k][j] + sum_e clip(kc[c][e],±5) * Wn1[k][192+e][j]
// ---------------------------------------------------------------------------
__global__ void kcbase_kernel(const float* __restrict__ kc,
                              const float* __restrict__ Wn1,
                              const float* __restrict__ bn1)
{
    __shared__ float skc[64];
    int c = blockIdx.x;
    int tid = threadIdx.x;              // 128
    if (tid < 64) skc[tid] = clampf(kc[c*64 + tid], -5.f, 5.f);
    __syncthreads();
    int k = tid >> 6, j = tid & 63;
    float a = bn1[k*64 + j];
    const float* Wp = Wn1 + k*16384 + 12288 + j;   // rows 192..255 of Wn1[k]
    #pragma unroll 8
    for (int e = 0; e < 64; e++) a = fmaf(skc[e], Wp[e*64], a);
    g_kcbase[((size_t)k*CC + c)*64 + j] = a;
}

// ---------------------------------------------------------------------------
// f1: m_next. Row-pair packed FFMA2, transposed activations, kcbase-folded.
// ---------------------------------------------------------------------------
__device__ __forceinline__ void gemm64_rp(ull acc[4][4], const float* W, const float* Xt, int rbase)
{
    #pragma unroll 8
    for (int kk = 0; kk < 64; kk++) {
        float4 w4 = *(const float4*)(W + kk*64);
        ull wd0=dup2(w4.x), wd1=dup2(w4.y), wd2=dup2(w4.z), wd3=dup2(w4.w);
        ulonglong2 ua = *(const ulonglong2*)(Xt + kk*RP1 + rbase);
        ulonglong2 ub = *(const ulonglong2*)(Xt + kk*RP1 + rbase + 4);
        fma2(acc[0][0],ua.x,wd0); fma2(acc[0][1],ua.x,wd1); fma2(acc[0][2],ua.x,wd2); fma2(acc[0][3],ua.x,wd3);
        fma2(acc[1][0],ua.y,wd0); fma2(acc[1][1],ua.y,wd1); fma2(acc[1][2],ua.y,wd2); fma2(acc[1][3],ua.y,wd3);
        fma2(acc[2][0],ub.x,wd0); fma2(acc[2][1],ub.x,wd1); fma2(acc[2][2],ub.x,wd2); fma2(acc[2][3],ub.x,wd3);
        fma2(acc[3][0],ub.y,wd0); fma2(acc[3][1],ub.y,wd1); fma2(acc[3][2],ub.y,wd2); fma2(acc[3][3],ub.y,wd3);
    }
}

__global__ void __launch_bounds__(256) f1_kernel(
    const int*   __restrict__ qt,  const float* __restrict__ ht,
    const float* __restrict__ oh,  const float* __restrict__ kc,
    const float* __restrict__ nwp,
    const float* __restrict__ Ws1, const float* __restrict__ bs1,
    const float* __restrict__ Ws2, const float* __restrict__ bs2,
    const float* __restrict__ Wn1, const float* __restrict__ Wn2,
    const float* __restrict__ bn2)
{
    extern __shared__ float sm[];
    float* sWn1 = sm;             // 8192  (ht-part rows 128..191, both k)
    float* sWn2 = sWn1 + 8192;    // 8192
    float* sbn2 = sWn2 + 8192;    // 128
    float* U_T  = sbn2 + 128;     // 64*132 = 8448  (clip(ht) transposed)
    float* H1_T = U_T  + 8448;    // 8448
    float* rmask= H1_T + 8448;    // 128
    float* radj = rmask + 128;    // 256
    float* xr   = radj + 256;     // 128 (masked-row scratch)
    float* hb   = xr + 128;       // 64
    __shared__ int s_mcnt;
    __shared__ int s_mrows[128];

    int tid = threadIdx.x;
    for (int i = tid; i < 8192; i += 256) {
        int k = i >> 12, rc = i & 4095;
        sWn1[i] = Wn1[k*16384 + 8192 + rc];   // rows 128..191 (ht part)
        sWn2[i] = Wn2[i];
    }
    if (tid < 128) sbn2[tid] = bn2[tid];
    float w = clampf(nwp[0], 0.1f, 0.9f);
    __syncthreads();

    int tr = tid >> 4, tc = tid & 15;
    int rbase = tr * 8, cbase = tc * 4;

    for (int tile = blockIdx.x; tile < NROWS/128; tile += gridDim.x) {
        int row0 = tile << 7;
        int c0 = row0 & 1023;
        if (tid == 0) s_mcnt = 0;
        __syncthreads();

        // U_T = clip(ht)^T
        for (int i = tid; i < 128*64; i += 256) {
            int r = i >> 6, j = i & 63;
            U_T[j*RP1 + r] = clampf(ht[(size_t)(row0+r)*64 + j], -5.f, 5.f);
        }
        if (tid < 128) {
            int gid = row0 + tid; int b = gid >> 10; int c = gid & 1023;
            float m = oh[(size_t)qt[b]*CC + c];
            rmask[tid] = m;
            radj[tid]       = g_adj[c];
            radj[128 + tid] = g_adj[CC + c];
            if (m > 0.5f) { int p = atomicAdd(&s_mcnt, 1); s_mrows[p] = tid; }
        }
        __syncthreads();

        float nf[8][4];
        #pragma unroll
        for (int k = 0; k < 2; k++) {
            // Stage A: H1 = relu(kcbase + clip(ht) @ Wn1_ht[k])
            ull acc[4][4];
            const float* kcb = g_kcbase + ((size_t)k*CC + c0 + rbase)*64 + cbase;
            #pragma unroll
            for (int p = 0; p < 4; p++) {
                float4 a = *(const float4*)(kcb + (2*p)*64);
                float4 b = *(const float4*)(kcb + (2*p+1)*64);
                acc[p][0]=pk2(a.x,b.x); acc[p][1]=pk2(a.y,b.y);
                acc[p][2]=pk2(a.z,b.z); acc[p][3]=pk2(a.w,b.w);
            }
            gemm64_rp(acc, sWn1 + k*4096 + cbase, U_T, rbase);
            #pragma unroll
            for (int p = 0; p < 4; p++)
                #pragma unroll
                for (int c = 0; c < 4; c++) {
                    float2 v = up2(acc[p][c]);
                    v.x = fmaxf(v.x, 0.f); v.y = fmaxf(v.y, 0.f);
                    *(float2*)(H1_T + (cbase+c)*RP1 + rbase + 2*p) = v;
                }
            __syncthreads();

            // Stage B: nb = clamp(H1 @ Wn2[k] + bn2[k], 0, 5); fold into nf
            #pragma unroll
            for (int c = 0; c < 4; c++) {
                ull b = dup2(sbn2[k*64 + cbase + c]);
                acc[0][c]=b; acc[1][c]=b; acc[2][c]=b; acc[3][c]=b;
            }
            gemm64_rp(acc, sWn2 + k*4096 + cbase, H1_T, rbase);
            #pragma unroll
            for (int p = 0; p < 4; p++) {
                float a0 = radj[k*128 + rbase + 2*p];
                float a1 = radj[k*128 + rbase + 2*p + 1];
                #pragma unroll
                for (int c = 0; c < 4; c++) {
                    float2 v = up2(acc[p][c]);
                    float v0 = a0 * clampf(v.x, 0.f, 5.f);
                    float v1 = a1 * clampf(v.y, 0.f, 5.f);
                    if (k == 0) {
                        nf[2*p][c]   = clampf(v0, -5.f, 5.f);
                        nf[2*p+1][c] = clampf(v1, -5.f, 5.f);
                    } else {
                        nf[2*p][c]   = clampf(w*nf[2*p][c]   + (1.f-w)*v0, -5.f, 5.f);
                        nf[2*p+1][c] = clampf(w*nf[2*p+1][c] + (1.f-w)*v1, -5.f, 5.f);
                    }
                }
            }
            __syncthreads();
        }

        // m_next for unmasked rows
        #pragma unroll
        for (int i = 0; i < 8; i++) {
            int r = rbase + i;
            if (rmask[r] <= 0.5f) {
                float4 o;
                o.x = clampf(nf[i][0], -50.f, 50.f);
                o.y = clampf(nf[i][1], -50.f, 50.f);
                o.z = clampf(nf[i][2], -50.f, 50.f);
                o.w = clampf(nf[i][3], -50.f, 50.f);
                *(float4*)(&g_mnext[(size_t)(row0 + r)*64 + cbase]) = o;
            }
        }

        // Rare masked rows: self MLP on RAW [ht, kc]
        int mcnt = s_mcnt;
        for (int mi = 0; mi < mcnt; mi++) {
            int r = s_mrows[mi]; int gid = row0 + r; int c = gid & 1023;
            if (tid < 128)
                xr[tid] = (tid < 64) ? ht[(size_t)gid*64 + tid] : kc[c*64 + tid - 64];
            __syncthreads();
            if (tid < 64) {
                float a = bs1[tid];
                for (int j = 0; j < 128; j++) a = fmaf(xr[j], Ws1[j*64 + tid], a);
                hb[tid] = fmaxf(a, 0.f);
            }
            __syncthreads();
            if (tid < 64) {
                float a = bs2[tid];
                for (int j = 0; j < 64; j++) a = fmaf(hb[j], Ws2[j*64 + tid], a);
                a = clampf(a, 0.f, 10.f);
                g_mnext[(size_t)gid*64 + tid] = clampf(a, -50.f, 50.f);
            }
            __syncthreads();
        }
        __syncthreads();
    }
}

// ---------------------------------------------------------------------------
// f2: edge-gate + fused GRU + head. Col-pair packed FFMA2.
// X_T[0:64] = m_next^T -> res^T (in place); X_T[64:128] = ht^T.
// ---------------------------------------------------------------------------
__global__ void __launch_bounds__(256) f2_kernel(
    const float* __restrict__ ht,  const float* __restrict__ ea_w,
    const float* __restrict__ We,  const float* __restrict__ be,
    const float* __restrict__ Wa,  const float* __restrict__ ba,
    const float* __restrict__ Wih, const float* __restrict__ bih,
    const float* __restrict__ Whh, const float* __restrict__ bhh,
    const float* __restrict__ Wp,  const float* __restrict__ bp,
    float* __restrict__ out)
{
    extern __shared__ float sm[];
    float* X_T  = sm;             // 128*68 = 8704
    float* sWe  = X_T  + 8704;    // 4096
    float* sWa  = sWe  + 4096;    // 4096
    float* sWrz = sWa  + 4096;    // 128*128 = 16384  ([Wih;Whh] cols 0..127)
    float* sWni = sWrz + 16384;   // 4096  (Wih cols 128..191)
    float* sWnh = sWni + 4096;    // 4096  (Whh cols 128..191)
    float* sbe  = sWnh + 4096;    // 64
    float* sba  = sbe  + 64;      // 64
    float* sbrz = sba  + 64;      // 128  (bih+bhh, r|z)
    float* sbni = sbrz + 128;     // 64
    float* sbnh = sbni + 64;      // 64
    float* sWp  = sbnh + 64;      // 64
    float* grow = sWp  + 64;      // 64

    int tid = threadIdx.x;
    for (int i = tid; i < 4096; i += 256) {
        int kk = i >> 6, c = i & 63;
        sWe[i]  = We[i];
        sWa[i]  = Wa[i];
        sWni[i] = Wih[kk*192 + 128 + c];
        sWnh[i] = Whh[kk*192 + 128 + c];
    }
    for (int i = tid; i < 16384; i += 256) {
        int kk = i >> 7, c = i & 127;
        sWrz[i] = (kk < 64) ? Wih[kk*192 + c] : Whh[(kk-64)*192 + c];
    }
    if (tid < 128) sbrz[tid] = bih[tid] + bhh[tid];
    if (tid < 64) {
        sbe[tid] = be[tid]; sba[tid] = ba[tid]; sWp[tid] = Wp[tid];
        sbni[tid] = bih[128+tid]; sbnh[tid] = bhh[128+tid];
    }
    float bpv = bp[0];
    __syncthreads();

    int tr = tid >> 4, tc = tid & 15;
    int rbase = tr * 4, cbase = tc * 4;

    for (int tile = blockIdx.x; tile < NROWS/64; tile += gridDim.x) {
        int row0 = tile << 6;
        for (int i = tid; i < 64*64; i += 256) {
            int r = i >> 6, j = i & 63;
            X_T[j*RP2 + r]        = g_mnext[(size_t)(row0+r)*64 + j];
            X_T[(64+j)*RP2 + r]   = ht     [(size_t)(row0+r)*64 + j];
        }
        if (tid < 64) grow[tid] = ea_w[(row0 + tid) & 1023];
        __syncthreads();

        // Phase A: S=M@We+be, T=M@Wa+ba (col-pair packed)
        ull aS[4][2], aT[4][2];
        {
            ulonglong2 be2 = *(const ulonglong2*)(sbe + cbase);
            ulonglong2 ba2 = *(const ulonglong2*)(sba + cbase);
            #pragma unroll
            for (int i = 0; i < 4; i++) {
                aS[i][0]=be2.x; aS[i][1]=be2.y;
                aT[i][0]=ba2.x; aT[i][1]=ba2.y;
            }
        }
        #pragma unroll 8
        for (int kk = 0; kk < 64; kk++) {
            float4 x4 = *(const float4*)(X_T + kk*RP2 + rbase);
            ull x0=dup2(x4.x), x1=dup2(x4.y), x2=dup2(x4.z), x3=dup2(x4.w);
            ulonglong2 we2 = *(const ulonglong2*)(sWe + kk*64 + cbase);
            ulonglong2 wa2 = *(const ulonglong2*)(sWa + kk*64 + cbase);
            fma2(aS[0][0],x0,we2.x); fma2(aS[0][1],x0,we2.y); fma2(aT[0][0],x0,wa2.x); fma2(aT[0][1],x0,wa2.y);
            fma2(aS[1][0],x1,we2.x); fma2(aS[1][1],x1,we2.y); fma2(aT[1][0],x1,wa2.x); fma2(aT[1][1],x1,wa2.y);
            fma2(aS[2][0],x2,we2.x); fma2(aS[2][1],x2,we2.y); fma2(aT[2][0],x2,wa2.x); fma2(aT[2][1],x2,wa2.y);
            fma2(aS[3][0],x3,we2.x); fma2(aS[3][1],x3,we2.y); fma2(aT[3][0],x3,wa2.x); fma2(aT[3][1],x3,wa2.y);
        }
        __syncthreads();   // all GEMM reads of M done
        #pragma unroll
        for (int i = 0; i < 4; i++) {
            int r = rbase + i; float g = grow[r];
            #pragma unroll
            for (int q = 0; q < 2; q++) {
                float2 s = up2(aS[i][q]);
                float2 t = up2(aT[i][q]);
                int c = cbase + 2*q;
                float m0 = X_T[c*RP2 + r], m1 = X_T[(c+1)*RP2 + r];
                X_T[c*RP2 + r]     = m0 - g*sigf(s.x)*m0 + g*tanhfast(t.x);
                X_T[(c+1)*RP2 + r] = m1 - g*sigf(s.y)*m1 + g*tanhfast(t.y);
            }
        }
        __syncthreads();

        // Phase B: fused r/z gate sums over K=128 ([res;ht] @ [Wih;Whh])
        ull aR[4][2], aZ[4][2];
        {
            ulonglong2 br2 = *(const ulonglong2*)(sbrz + cbase);
            ulonglong2 bz2 = *(const ulonglong2*)(sbrz + 64 + cbase);
            #pragma unroll
            for (int i = 0; i < 4; i++) {
                aR[i][0]=br2.x; aR[i][1]=br2.y;
                aZ[i][0]=bz2.x; aZ[i][1]=bz2.y;
            }
        }
        #pragma unroll 8
        for (int kk = 0; kk < 128; kk++) {
            float4 x4 = *(const float4*)(X_T + kk*RP2 + rbase);
            ull x0=dup2(x4.x), x1=dup2(x4.y), x2=dup2(x4.z), x3=dup2(x4.w);
            ulonglong2 wr2 = *(const ulonglong2*)(sWrz + kk*128 + cbase);
            ulonglong2 wz2 = *(const ulonglong2*)(sWrz + kk*128 + 64 + cbase);
            fma2(aR[0][0],x0,wr2.x); fma2(aR[0][1],x0,wr2.y); fma2(aZ[0][0],x0,wz2.x); fma2(aZ[0][1],x0,wz2.y);
            fma2(aR[1][0],x1,wr2.x); fma2(aR[1][1],x1,wr2.y); fma2(aZ[1][0],x1,wz2.x); fma2(aZ[1][1],x1,wz2.y);
            fma2(aR[2][0],x2,wr2.x); fma2(aR[2][1],x2,wr2.y); fma2(aZ[2][0],x2,wz2.x); fma2(aZ[2][1],x2,wz2.y);
            fma2(aR[3][0],x3,wr2.x); fma2(aR[3][1],x3,wr2.y); fma2(aZ[3][0],x3,wz2.x); fma2(aZ[3][1],x3,wz2.y);
        }
        float rg[4][4], zg[4][4];
        #pragma unroll
        for (int i = 0; i < 4; i++)
            #pragma unroll
            for (int q = 0; q < 2; q++) {
                float2 vr = up2(aR[i][q]);
                float2 vz = up2(aZ[i][q]);
                rg[i][2*q] = sigf(vr.x); rg[i][2*q+1] = sigf(vr.y);
                zg[i][2*q] = sigf(vz.x); zg[i][2*q+1] = sigf(vz.y);
            }

        // Phase C: n gate (in_ and hn separate), h_next, y
        ull aI[4][2], aH[4][2];
        {
            ulonglong2 bi2 = *(const ulonglong2*)(sbni + cbase);
            ulonglong2 bh2 = *(const ulonglong2*)(sbnh + cbase);
            #pragma unroll
            for (int i = 0; i < 4; i++) {
                aI[i][0]=bi2.x; aI[i][1]=bi2.y;
                aH[i][0]=bh2.x; aH[i][1]=bh2.y;
            }
        }
        #pragma unroll 8
        for (int kk = 0; kk < 64; kk++) {
            float4 x4 = *(const float4*)(X_T + kk*RP2 + rbase);
            ull x0=dup2(x4.x), x1=dup2(x4.y), x2=dup2(x4.z), x3=dup2(x4.w);
            ulonglong2 wi2 = *(const ulonglong2*)(sWni + kk*64 + cbase);
            fma2(aI[0][0],x0,wi2.x); fma2(aI[0][1],x0,wi2.y);
            fma2(aI[1][0],x1,wi2.x); fma2(aI[1][1],x1,wi2.y);
            fma2(aI[2][0],x2,wi2.x); fma2(aI[2][1],x2,wi2.y);
            fma2(aI[3][0],x3,wi2.x); fma2(aI[3][1],x3,wi2.y);
        }
        #pragma unroll 8
        for (int kk = 0; kk < 64; kk++) {
            float4 h4 = *(const float4*)(X_T + (64+kk)*RP2 + rbase);
            ull h0=dup2(h4.x), h1=dup2(h4.y), h2=dup2(h4.z), h3=dup2(h4.w);
            ulonglong2 wh2 = *(const ulonglong2*)(sWnh + kk*64 + cbase);
            fma2(aH[0][0],h0,wh2.x); fma2(aH[0][1],h0,wh2.y);
            fma2(aH[1][0],h1,wh2.x); fma2(aH[1][1],h1,wh2.y);
            fma2(aH[2][0],h2,wh2.x); fma2(aH[2][1],h2,wh2.y);
            fma2(aH[3][0],h3,wh2.x); fma2(aH[3][1],h3,wh2.y);
        }
        #pragma unroll
        for (int i = 0; i < 4; i++) {
            int r = rbase + i;
            float py = 0.f;
            #pragma unroll
            for (int q = 0; q < 2; q++) {
                float2 vi = up2(aI[i][q]);
                float2 vh = up2(aH[i][q]);
                int c = cbase + 2*q;
                float n0 = tanhfast(vi.x + rg[i][2*q]   * vh.x);
                float n1 = tanhfast(vi.y + rg[i][2*q+1] * vh.y);
                float h0 = X_T[(64+c)*RP2 + r];
                float h1 = X_T[(64+c+1)*RP2 + r];
                float z0 = zg[i][2*q], z1 = zg[i][2*q+1];
                float hn0 = (1.f - z0)*n0 + z0*h0;
                float hn1 = (1.f - z1)*n1 + z1*h1;
                py = fmaf(hn0, sWp[c],   py);
                py = fmaf(hn1, sWp[c+1], py);
            }
            py += __shfl_down_sync(0xffffffffu, py, 8, 16);
            py += __shfl_down_sync(0xffffffffu, py, 4, 16);
            py += __shfl_down_sync(0xffffffffu, py, 2, 16);
            py += __shfl_down_sync(0xffffffffu, py, 1, 16);
            if (tc == 0) out[row0 + r] = sigf(py + bpv);
        }
        __syncthreads();
    }
}

// ---------------------------------------------------------------------------
extern "C" void kernel_launch(void* const* d_in, const int* in_sizes, int n_in,
                              void* d_out, int out_size)
{
    const int*   qt  = (const int*)  d_in[1];
    const float* ht  = (const float*)d_in[2];
    const float* oh  = (const float*)d_in[3];
    const float* kc  = (const float*)d_in[4];
    const float* gr  = (const float*)d_in[5];
    const float* nw  = (const float*)d_in[6];
    const float* Ws1 = (const float*)d_in[7];
    const float* bs1 = (const float*)d_in[8];
    const float* Ws2 = (const float*)d_in[9];
    const float* bs2 = (const float*)d_in[10];
    const float* Wn1 = (const float*)d_in[11];
    const float* bn1 = (const float*)d_in[12];
    const float* Wn2 = (const float*)d_in[13];
    const float* bn2 = (const float*)d_in[14];
    const float* ea  = (const float*)d_in[15];
    const float* We  = (const float*)d_in[16];
    const float* be  = (const float*)d_in[17];
    const float* Wa  = (const float*)d_in[18];
    const float* ba  = (const float*)d_in[19];
    const float* Wih = (const float*)d_in[20];
    const float* bih = (const float*)d_in[21];
    const float* Whh = (const float*)d_in[22];
    const float* bhh = (const float*)d_in[23];
    const float* Wp  = (const float*)d_in[24];
    const float* bp  = (const float*)d_in[25];
    float* out = (float*)d_out;

    int smc = 148;
    if (cudaDeviceGetAttribute(&smc, cudaDevAttrMultiProcessorCount, 0) != cudaSuccess || smc <= 0)
        smc = 148;

    size_t smem1 = (size_t)(8192+8192+128+8448+8448+128+256+128+64) * 4;                  // 135,936 B
    size_t smem2 = (size_t)(8704+4096+4096+16384+4096+4096+64+64+128+64+64+64+64) * 4;    // 167,936 B
    cudaFuncSetAttribute(f1_kernel, cudaFuncAttributeMaxDynamicSharedMemorySize, (int)smem1);
    cudaFuncSetAttribute(f2_kernel, cudaFuncAttributeMaxDynamicSharedMemorySize, (int)smem2);

    adj_kernel<<<1, 1024>>>(qt, oh, gr);
    kcbase_kernel<<<1024, 128>>>(kc, Wn1, bn1);
    f1_kernel<<<smc, 256, smem1>>>(qt, ht, oh, kc, nw, Ws1, bs1, Ws2, bs2, Wn1, Wn2, bn2);
    f2_kernel<<<smc, 256, smem2>>>(ht, ea, We, be, Wa, ba, Wih, bih, Whh, bhh, Wp, bp, out);
}